// round 13
// baseline (speedup 1.0000x reference)
#include <cuda_runtime.h>
#include <cuda_bf16.h>

// CenterLoss == per-row gathered squared distance:
// loss = [ sum_b clip(||x_b - c_{l_b}||^2, 1e-12, 1e12) + B*(C-1)*1e-12 ] / B
//
// Inputs: x [B, D] f32, labels [B] int32, centers [C, D] f32. Output: scalar f32.
//
// R13: continue the R12 direction (fewer CTAs, same total threads).
// 256 CTAs x 1024 thr, 16 rows/CTA, 64 thr/row, 2 x-float4 + 2 c-float4
// per thread (MLP=4). Fence-free release/acq_rel tail, scattered 32-slot
// accumulation, parallel last-CTA gather.

#define BATCH 4096
#define FEAT 512
#define NCLASSES 10000
#define THREADS 1024
#define ROWS_PER_CTA 16
#define NBLOCKS (BATCH / ROWS_PER_CTA)   // 256
#define NSLOTS 32

__device__ float g_part[NSLOTS * 32];    // every 32nd float: 128B stride
__device__ unsigned int g_count = 0;

__device__ __forceinline__ void red_add_release(float* addr, float v) {
    asm volatile("red.release.gpu.global.add.f32 [%0], %1;"
                 :: "l"(addr), "f"(v) : "memory");
}
__device__ __forceinline__ unsigned atomic_inc_acq_rel(unsigned* addr, unsigned wrap) {
    unsigned old;
    asm volatile("atom.acq_rel.gpu.global.inc.u32 %0, [%1], %2;"
                 : "=r"(old) : "l"(addr), "r"(wrap) : "memory");
    return old;
}

__global__ __launch_bounds__(THREADS) void center_loss_kernel(
    const float* __restrict__ x,
    const int* __restrict__ labels,
    const float* __restrict__ centers,
    float* __restrict__ out)
{
    const int tid    = threadIdx.x;
    const int warp   = tid >> 5;          // 0..31
    const int lane   = tid & 31;
    const int rid    = tid >> 6;          // row within CTA: 0..15 (2 warps/row)
    const int lane64 = tid & 63;          // thread within row
    const int row    = blockIdx.x * ROWS_PER_CTA + rid;

    // const-path uniform broadcast label load heads the dependency chain
    int lbl = __ldg(labels + row);
    lbl = min(max(lbl, 0), NCLASSES - 1);

    // 512 floats = 128 float4 per row; 64 threads x 2 float4 each
    const float4* xr = reinterpret_cast<const float4*>(x + (size_t)row * FEAT);
    const float4* cr = reinterpret_cast<const float4*>(centers + (size_t)lbl * FEAT);

    float4 x0 = __ldg(xr + lane64);
    float4 x1 = __ldg(xr + lane64 + 64);
    float4 c0 = __ldg(cr + lane64);
    float4 c1 = __ldg(cr + lane64 + 64);

    float d0 = x0.x - c0.x, d1 = x0.y - c0.y, d2 = x0.z - c0.z, d3 = x0.w - c0.w;
    float e0 = x1.x - c1.x, e1 = x1.y - c1.y, e2 = x1.z - c1.z, e3 = x1.w - c1.w;
    float s = d0 * d0 + d1 * d1 + d2 * d2 + d3 * d3
            + e0 * e0 + e1 * e1 + e2 * e2 + e3 * e3;

    // warp reduce
#pragma unroll
    for (int off = 16; off > 0; off >>= 1)
        s += __shfl_xor_sync(0xFFFFFFFFu, s, off);

    __shared__ float warp_sums[32];
    if (lane == 0) warp_sums[warp] = s;
    __syncthreads();

    if (warp == 0) {
        // row r = warp_sums[2r] + warp_sums[2r+1]; faithful per-entry clamp
        float p = 0.0f;
        if (lane < ROWS_PER_CTA) {
            float d = warp_sums[2 * lane] + warp_sums[2 * lane + 1];
            p = fminf(fmaxf(d, 1e-12f), 1e12f);
        }
#pragma unroll
        for (int off = 8; off > 0; off >>= 1)
            p += __shfl_xor_sync(0xFFFFFFFFu, p, off);

        unsigned done = 0;
        if (lane == 0) {
            // release add: visible before (and ordered with) the count inc
            red_add_release(&g_part[(blockIdx.x & (NSLOTS - 1)) * 32], p);
            done = (atomic_inc_acq_rel(&g_count, NBLOCKS - 1) == NBLOCKS - 1) ? 1u : 0u;
        }
        done = __shfl_sync(0xFFFFFFFFu, done, 0);

        if (done) {
            // parallel slot gather: lane i owns slot i (independent 128B lines)
            float t = g_part[lane * 32];
            g_part[lane * 32] = 0.0f;     // reset for next graph replay
#pragma unroll
            for (int off = 16; off > 0; off >>= 1)
                t += __shfl_xor_sync(0xFFFFFFFFu, t, off);
            if (lane == 0) {
                out[0] = t * (1.0f / (float)BATCH)
                       + (float)((double)(NCLASSES - 1) * 1e-12);
            }
        }
    }
}

extern "C" void kernel_launch(void* const* d_in, const int* in_sizes, int n_in,
                              void* d_out, int out_size) {
    const float* x = (const float*)d_in[0];
    const int* labels = (const int*)d_in[1];
    const float* centers = (const float*)d_in[2];
    float* out = (float*)d_out;

    center_loss_kernel<<<NBLOCKS, THREADS>>>(x, labels, centers, out);
}

// round 14
// speedup vs baseline: 1.0257x; 1.0257x over previous
#include <cuda_runtime.h>
#include <cuda_bf16.h>

// CenterLoss == per-row gathered squared distance:
// loss = [ sum_b clip(||x_b - c_{l_b}||^2, 1e-12, 1e12) + B*(C-1)*1e-12 ] / B
//
// Inputs: x [B, D] f32, labels [B] int32, centers [C, D] f32. Output: scalar f32.
//
// FINAL (= R12, the measured optimum of the CTA-count sweep: 1024->8.26us,
// 512->7.84us, 256->8.64us ncu). 512 CTAs x 512 thr, 8 rows/CTA, 64 thr/row,
// 2 x-float4 + 2 c-float4 per thread (MLP=4). Single launch, fence-free
// release/acq_rel epilogue, scattered 32-slot accumulation, parallel
// last-CTA gather; moves the 16MB working set exactly once (~2 TB/s achieved).

#define BATCH 4096
#define FEAT 512
#define NCLASSES 10000
#define THREADS 512
#define ROWS_PER_CTA 8
#define NBLOCKS (BATCH / ROWS_PER_CTA)   // 512
#define NSLOTS 32

__device__ float g_part[NSLOTS * 32];    // every 32nd float: 128B stride
__device__ unsigned int g_count = 0;

__device__ __forceinline__ void red_add_release(float* addr, float v) {
    asm volatile("red.release.gpu.global.add.f32 [%0], %1;"
                 :: "l"(addr), "f"(v) : "memory");
}
__device__ __forceinline__ unsigned atomic_inc_acq_rel(unsigned* addr, unsigned wrap) {
    unsigned old;
    asm volatile("atom.acq_rel.gpu.global.inc.u32 %0, [%1], %2;"
                 : "=r"(old) : "l"(addr), "r"(wrap) : "memory");
    return old;
}

__global__ __launch_bounds__(THREADS) void center_loss_kernel(
    const float* __restrict__ x,
    const int* __restrict__ labels,
    const float* __restrict__ centers,
    float* __restrict__ out)
{
    const int tid    = threadIdx.x;
    const int warp   = tid >> 5;          // 0..15
    const int lane   = tid & 31;
    const int rid    = tid >> 6;          // row within CTA: 0..7 (2 warps/row)
    const int lane64 = tid & 63;          // thread within row
    const int row    = blockIdx.x * ROWS_PER_CTA + rid;

    // const-path uniform broadcast label load heads the dependency chain
    int lbl = __ldg(labels + row);
    lbl = min(max(lbl, 0), NCLASSES - 1);

    // 512 floats = 128 float4 per row; 64 threads x 2 float4 each
    const float4* xr = reinterpret_cast<const float4*>(x + (size_t)row * FEAT);
    const float4* cr = reinterpret_cast<const float4*>(centers + (size_t)lbl * FEAT);

    float4 x0 = __ldg(xr + lane64);
    float4 x1 = __ldg(xr + lane64 + 64);
    float4 c0 = __ldg(cr + lane64);
    float4 c1 = __ldg(cr + lane64 + 64);

    float d0 = x0.x - c0.x, d1 = x0.y - c0.y, d2 = x0.z - c0.z, d3 = x0.w - c0.w;
    float e0 = x1.x - c1.x, e1 = x1.y - c1.y, e2 = x1.z - c1.z, e3 = x1.w - c1.w;
    float s = d0 * d0 + d1 * d1 + d2 * d2 + d3 * d3
            + e0 * e0 + e1 * e1 + e2 * e2 + e3 * e3;

    // warp reduce
#pragma unroll
    for (int off = 16; off > 0; off >>= 1)
        s += __shfl_xor_sync(0xFFFFFFFFu, s, off);

    __shared__ float warp_sums[16];
    if (lane == 0) warp_sums[warp] = s;
    __syncthreads();

    if (warp == 0) {
        // row r = warp_sums[2r] + warp_sums[2r+1]; faithful per-entry clamp
        float p = 0.0f;
        if (lane < ROWS_PER_CTA) {
            float d = warp_sums[2 * lane] + warp_sums[2 * lane + 1];
            p = fminf(fmaxf(d, 1e-12f), 1e12f);
        }
#pragma unroll
        for (int off = 4; off > 0; off >>= 1)
            p += __shfl_xor_sync(0xFFFFFFFFu, p, off);

        unsigned done = 0;
        if (lane == 0) {
            // release add: visible before (and ordered with) the count inc
            red_add_release(&g_part[(blockIdx.x & (NSLOTS - 1)) * 32], p);
            done = (atomic_inc_acq_rel(&g_count, NBLOCKS - 1) == NBLOCKS - 1) ? 1u : 0u;
        }
        done = __shfl_sync(0xFFFFFFFFu, done, 0);

        if (done) {
            // parallel slot gather: lane i owns slot i (independent 128B lines)
            float t = g_part[lane * 32];
            g_part[lane * 32] = 0.0f;     // reset for next graph replay
#pragma unroll
            for (int off = 16; off > 0; off >>= 1)
                t += __shfl_xor_sync(0xFFFFFFFFu, t, off);
            if (lane == 0) {
                out[0] = t * (1.0f / (float)BATCH)
                       + (float)((double)(NCLASSES - 1) * 1e-12);
            }
        }
    }
}

extern "C" void kernel_launch(void* const* d_in, const int* in_sizes, int n_in,
                              void* d_out, int out_size) {
    const float* x = (const float*)d_in[0];
    const int* labels = (const int*)d_in[1];
    const float* centers = (const float*)d_in[2];
    float* out = (float*)d_out;

    center_loss_kernel<<<NBLOCKS, THREADS>>>(x, labels, centers, out);
}